// round 5
// baseline (speedup 1.0000x reference)
#include <cuda_runtime.h>

#define NN 100000
#define NE 1600000
#define OD 64
#define ID 256

// scratch: pre_sup for both supports, [2][NN][OD]
__device__ float g_pre[2 * NN * OD];

__global__ void __launch_bounds__(256) zero_out_kernel(float4* __restrict__ out, int n4) {
    int i = blockIdx.x * 256 + threadIdx.x;
    if (i < n4) out[i] = make_float4(0.f, 0.f, 0.f, 0.f);
}

// GEMM: g_pre[s][m][o] = sum_k x[m][k] * W[s][k][o]
// Treated as M x 256 @ 256 x 128 where cols [0..63] = W0, [64..127] = W1.
// Block tile 128x128, 256 threads, 8x8 per thread, BK=8.
__global__ void __launch_bounds__(256) gemm128_kernel(const float* __restrict__ X,
                                                      const float* __restrict__ W) {
    __shared__ float As[8][128];   // [k][m]
    __shared__ float Bs[8][128];   // [k][n]
    const int tid = threadIdx.x;
    const int brow = blockIdx.x * 128;
    const int tr = tid >> 4;       // 0..15
    const int tc = tid & 15;       // 0..15

    float acc[8][8];
#pragma unroll
    for (int i = 0; i < 8; i++)
#pragma unroll
        for (int j = 0; j < 8; j++) acc[i][j] = 0.f;

    // A-load mapping: 128 rows x 8 k = 256 float4 (one per thread)
    const int a_row = tid >> 1;             // 0..127
    const int a_k   = (tid & 1) << 2;       // 0 or 4
    // B-load mapping: 8 k x 32 float4-cols
    const int b_k   = tid >> 5;             // 0..7
    const int b_n4  = tid & 31;             // 0..31
    const int b_sup = b_n4 >> 4;            // 0 or 1
    const int b_in  = (b_n4 & 15) << 2;     // 0..60

    const bool a_ok = (brow + a_row) < NN;
    const float* xp = X + (size_t)(brow + a_row) * ID + a_k;
    const float* wp = W + (size_t)b_sup * (ID * OD) + (size_t)b_k * OD + b_in;

    for (int k0 = 0; k0 < ID; k0 += 8) {
        float4 av = make_float4(0.f, 0.f, 0.f, 0.f);
        if (a_ok) av = *reinterpret_cast<const float4*>(xp + k0);
        float4 bv = *reinterpret_cast<const float4*>(wp + (size_t)k0 * OD);

        As[a_k + 0][a_row] = av.x;
        As[a_k + 1][a_row] = av.y;
        As[a_k + 2][a_row] = av.z;
        As[a_k + 3][a_row] = av.w;
        *reinterpret_cast<float4*>(&Bs[b_k][b_n4 << 2]) = bv;
        __syncthreads();

#pragma unroll
        for (int kk = 0; kk < 8; kk++) {
            float a[8], b[8];
            *reinterpret_cast<float4*>(a)     = *reinterpret_cast<const float4*>(&As[kk][tr * 8]);
            *reinterpret_cast<float4*>(a + 4) = *reinterpret_cast<const float4*>(&As[kk][tr * 8 + 4]);
            *reinterpret_cast<float4*>(b)     = *reinterpret_cast<const float4*>(&Bs[kk][tc * 8]);
            *reinterpret_cast<float4*>(b + 4) = *reinterpret_cast<const float4*>(&Bs[kk][tc * 8 + 4]);
#pragma unroll
            for (int i = 0; i < 8; i++)
#pragma unroll
                for (int j = 0; j < 8; j++) acc[i][j] += a[i] * b[j];
        }
        __syncthreads();
    }

    // store: cols tc*8..tc*8+7 lie entirely inside one support (tc*8 aligned to 8)
    const int sup = tc >> 3;
    const int o = (tc * 8) & 63;
    float* dbase = g_pre + (size_t)sup * NN * OD + o;
#pragma unroll
    for (int i = 0; i < 8; i++) {
        int m = brow + tr * 8 + i;
        if (m < NN) {
            float4 v0 = make_float4(acc[i][0], acc[i][1], acc[i][2], acc[i][3]);
            float4 v1 = make_float4(acc[i][4], acc[i][5], acc[i][6], acc[i][7]);
            *reinterpret_cast<float4*>(dbase + (size_t)m * OD)     = v0;
            *reinterpret_cast<float4*>(dbase + (size_t)m * OD + 4) = v1;
        }
    }
}

// SPMM scatter: 16 threads per (support, edge); each handles one float4 of the
// 64-wide row. Gather from g_pre (L2-resident), scale by edge_val, vector RED
// (no-return atomic) into out.
__global__ void __launch_bounds__(256) spmm_kernel(const float* __restrict__ ev,
                                                   const int* __restrict__ es,
                                                   const int* __restrict__ ed,
                                                   float* __restrict__ out) {
    int idx = blockIdx.x * 256 + threadIdx.x;
    int e = idx >> 4;               // 0 .. 2*NE-1 (arrays are [2][NE] contiguous)
    if (e >= 2 * NE) return;
    int t = idx & 15;

    int src  = __ldg(es + e);
    int dst  = __ldg(ed + e);
    float val = __ldg(ev + e);
    int sup = (e >= NE) ? 1 : 0;

    const float4* prow =
        reinterpret_cast<const float4*>(g_pre + (size_t)sup * NN * OD + (size_t)src * OD);
    float4 v = __ldg(prow + t);

    float* addr = out + (size_t)dst * OD + t * 4;
    asm volatile("red.global.add.v4.f32 [%0], {%1, %2, %3, %4};"
                 :: "l"(addr), "f"(v.x * val), "f"(v.y * val), "f"(v.z * val), "f"(v.w * val)
                 : "memory");
}

__global__ void __launch_bounds__(256) relu_kernel(float4* __restrict__ out, int n4) {
    int i = blockIdx.x * 256 + threadIdx.x;
    if (i < n4) {
        float4 v = out[i];
        v.x = fmaxf(v.x, 0.f);
        v.y = fmaxf(v.y, 0.f);
        v.z = fmaxf(v.z, 0.f);
        v.w = fmaxf(v.w, 0.f);
        out[i] = v;
    }
}

extern "C" void kernel_launch(void* const* d_in, const int* in_sizes, int n_in,
                              void* d_out, int out_size) {
    const float* x  = (const float*)d_in[0];   // [NN, 256]
    const float* W  = (const float*)d_in[1];   // [2, 256, 64]
    const float* ev = (const float*)d_in[2];   // [2, NE]
    const int*   es = (const int*)d_in[3];     // [2, NE]
    const int*   ed = (const int*)d_in[4];     // [2, NE]
    float* out = (float*)d_out;                // [NN, 64]

    const int n4 = NN * OD / 4;  // 1.6M float4

    zero_out_kernel<<<(n4 + 255) / 256, 256>>>((float4*)out, n4);
    gemm128_kernel<<<(NN + 127) / 128, 256>>>(x, W);

    const long long total = (long long)2 * NE * 16;
    spmm_kernel<<<(int)((total + 255) / 256), 256>>>(ev, es, ed, out);

    relu_kernel<<<(n4 + 255) / 256, 256>>>((float4*)out, n4);
}